// round 1
// baseline (speedup 1.0000x reference)
#include <cuda_runtime.h>

#define N_PTS 2048
#define M_PTS 512
#define HID   128
#define TJ    64
#define JT    (M_PTS / TJ)   // 8 j-tiles
#define PI_F  3.14159265358979323846f

// Scratch (device globals: no allocations allowed)
__device__ __align__(16) float g_A[N_PTS * HID];     // input @ W1[0:2]
__device__ __align__(16) float g_B[M_PTS * HID];     // quad_x @ W1[2:4] + b1
__device__ __align__(16) float g_y[M_PTS];           // quadrature weights
__device__ float g_Y;                                // sum of y
__device__ __align__(16) float g_part[N_PTS * JT];   // per (i, j-tile) partial sums

// Accurate-enough fast tanh: 1 - 2/(exp(2x)+1).
// __expf (ex2.approx, ~2^-22 rel err) + MUFU.RCP -> ~1e-6 abs error, robust at +/-inf.
__device__ __forceinline__ float tanh_fast(float x) {
    float e = __expf(2.0f * x);
    return 1.0f - __fdividef(2.0f, e + 1.0f);
}

// ---------------------------------------------------------------------------
// Precompute A[n][h] and B[m][h] (layer-1 factorization)
// ---------------------------------------------------------------------------
__global__ void prep_ab_kernel(const float* __restrict__ inp,
                               const float* __restrict__ qx,
                               const float* __restrict__ W1,
                               const float* __restrict__ b1) {
    int idx = blockIdx.x * blockDim.x + threadIdx.x;
    const float4* W14 = (const float4*)W1;   // W1 is [4][128] row-major
    if (idx < N_PTS * 32) {
        int n = idx >> 5, v = idx & 31;
        float x0 = inp[2 * n], x1 = inp[2 * n + 1];
        float4 wa = W14[v], wb = W14[32 + v];
        float4 r;
        r.x = x0 * wa.x + x1 * wb.x;
        r.y = x0 * wa.y + x1 * wb.y;
        r.z = x0 * wa.z + x1 * wb.z;
        r.w = x0 * wa.w + x1 * wb.w;
        ((float4*)g_A)[idx] = r;
    } else {
        int t = idx - N_PTS * 32;
        if (t < M_PTS * 32) {
            int m = t >> 5, v = t & 31;
            float q0 = qx[2 * m], q1 = qx[2 * m + 1];
            float4 wc = W14[64 + v], wd = W14[96 + v];
            float4 bb = ((const float4*)b1)[v];
            float4 r;
            r.x = q0 * wc.x + q1 * wd.x + bb.x;
            r.y = q0 * wc.y + q1 * wd.y + bb.y;
            r.z = q0 * wc.z + q1 * wd.z + bb.z;
            r.w = q0 * wc.w + q1 * wd.w + bb.w;
            ((float4*)g_B)[t] = r;
        }
    }
}

// ---------------------------------------------------------------------------
// Quadrature weights y[j] = prod_d sin(pi * e * q[j][d]), plus Y = sum y
// ---------------------------------------------------------------------------
__global__ void prep_y_kernel(const float* __restrict__ qx,
                              const float* __restrict__ ep) {
    __shared__ float red[512];
    int j = threadIdx.x;
    float e = ep[0];
    float y = sinf(PI_F * e * qx[2 * j]) * sinf(PI_F * e * qx[2 * j + 1]);
    g_y[j] = y;
    red[j] = y;
    __syncthreads();
    for (int s = 256; s > 0; s >>= 1) {
        if (j < s) red[j] += red[j + s];
        __syncthreads();
    }
    if (j == 0) g_Y = red[0];
}

// ---------------------------------------------------------------------------
// Main fused kernel: h1 tile -> GEMM with W2 -> tanh -> dot W3 -> y-weighted sum
// CTA = (i, j-tile of 64). 256 threads, 8 warps.
// Warp w owns pairs p = w*8 .. w*8+7; lane owns k = lane*4 .. lane*4+3.
// ---------------------------------------------------------------------------
__global__ void __launch_bounds__(256, 2) modnet_main_kernel(
        const float* __restrict__ W2,
        const float* __restrict__ b2,
        const float* __restrict__ W3) {
    extern __shared__ float sm[];
    float* h1s = sm;                       // [TJ][129]  (pitch 129: conflict-free)
    float* w2s = sm + TJ * 129;            // [128][128]
    float* red = w2s + HID * HID;          // [8]

    const int i   = blockIdx.y;
    const int jt  = blockIdx.x;
    const int j0  = jt * TJ;
    const int tid = threadIdx.x;
    const int lane = tid & 31;
    const int wrp  = tid >> 5;

    // ---- fill h1 tile: tanh(A[i] + B[j]) ----
    const float4* A4 = ((const float4*)g_A) + i * 32;
    const float4* B4 = ((const float4*)g_B) + j0 * 32;
    for (int e2 = tid; e2 < TJ * 32; e2 += 256) {
        int p = e2 >> 5, v = e2 & 31;
        float4 a = A4[v];
        float4 b = B4[e2];                 // (p*32 + v) == e2
        float* dst = h1s + p * 129 + v * 4;
        dst[0] = tanh_fast(a.x + b.x);
        dst[1] = tanh_fast(a.y + b.y);
        dst[2] = tanh_fast(a.z + b.z);
        dst[3] = tanh_fast(a.w + b.w);
    }
    // ---- cache W2 ----
    {
        const float4* W24 = (const float4*)W2;
        float4* w2s4 = (float4*)w2s;
        for (int e2 = tid; e2 < HID * 32; e2 += 256) w2s4[e2] = W24[e2];
    }
    __syncthreads();

    // ---- register-tiled GEMM: acc[pp][kk] = sum_c h1[p][c] * W2[c][k] ----
    float acc[8][4];
    #pragma unroll
    for (int pp = 0; pp < 8; pp++)
        #pragma unroll
        for (int kk = 0; kk < 4; kk++) acc[pp][kk] = 0.0f;

    const float* h1p = h1s + (wrp * 8) * 129;
    const float* w2p = w2s + lane * 4;

    #pragma unroll 4
    for (int c = 0; c < HID; ++c) {
        float4 bv = *(const float4*)(w2p + c * HID);
        float av[8];
        #pragma unroll
        for (int pp = 0; pp < 8; pp++) av[pp] = h1p[pp * 129 + c];  // warp-uniform broadcast
        #pragma unroll
        for (int pp = 0; pp < 8; pp++) {
            acc[pp][0] += av[pp] * bv.x;
            acc[pp][1] += av[pp] * bv.y;
            acc[pp][2] += av[pp] * bv.z;
            acc[pp][3] += av[pp] * bv.w;
        }
    }

    // ---- epilogue: tanh, dot W3, reduce over k (lanes), weight by y[j] ----
    const int kb = lane * 4;
    float4 b2v = *(const float4*)(b2 + kb);
    float4 w3v = *(const float4*)(W3 + kb);

    float s = 0.0f;
    #pragma unroll
    for (int pp = 0; pp < 8; pp++) {
        float g = tanh_fast(acc[pp][0] + b2v.x) * w3v.x
                + tanh_fast(acc[pp][1] + b2v.y) * w3v.y
                + tanh_fast(acc[pp][2] + b2v.z) * w3v.z
                + tanh_fast(acc[pp][3] + b2v.w) * w3v.w;
        #pragma unroll
        for (int o = 16; o > 0; o >>= 1) g += __shfl_xor_sync(0xffffffffu, g, o);
        if (lane == 0) s += g * g_y[j0 + wrp * 8 + pp];
    }
    if (lane == 0) red[wrp] = s;
    __syncthreads();
    if (tid == 0) {
        float t = 0.0f;
        #pragma unroll
        for (int w = 0; w < 8; w++) t += red[w];   // fixed order: deterministic
        g_part[i * JT + jt] = t;
    }
}

// ---------------------------------------------------------------------------
// Finalize: out[i] = b3*Y + sum over j-tiles (deterministic order)
// ---------------------------------------------------------------------------
__global__ void finalize_kernel(const float* __restrict__ b3,
                                float* __restrict__ out) {
    int i = blockIdx.x * blockDim.x + threadIdx.x;
    if (i < N_PTS) {
        float s = b3[0] * g_Y;
        #pragma unroll
        for (int t = 0; t < JT; t++) s += g_part[i * JT + t];
        out[i] = s;
    }
}

// ---------------------------------------------------------------------------
extern "C" void kernel_launch(void* const* d_in, const int* in_sizes, int n_in,
                              void* d_out, int out_size) {
    const float* inp = (const float*)d_in[0];   // [2048, 2]
    const float* qx  = (const float*)d_in[1];   // [512, 2]
    const float* ep  = (const float*)d_in[2];   // [1]
    const float* W1  = (const float*)d_in[3];   // [4, 128]
    const float* b1  = (const float*)d_in[4];   // [128]
    const float* W2  = (const float*)d_in[5];   // [128, 128]
    const float* b2  = (const float*)d_in[6];   // [128]
    const float* W3  = (const float*)d_in[7];   // [128, 1]
    const float* b3  = (const float*)d_in[8];   // [1]
    float* out = (float*)d_out;                 // [2048, 1]

    (void)in_sizes; (void)n_in; (void)out_size;

    const int smem = (TJ * 129 + HID * HID + 8) * (int)sizeof(float);  // 98592 B
    cudaFuncSetAttribute(modnet_main_kernel,
                         cudaFuncAttributeMaxDynamicSharedMemorySize, smem);

    prep_ab_kernel<<<(N_PTS * 32 + M_PTS * 32 + 255) / 256, 256>>>(inp, qx, W1, b1);
    prep_y_kernel<<<1, 512>>>(qx, ep);
    modnet_main_kernel<<<dim3(JT, N_PTS), 256, smem>>>(W2, b2, W3);
    finalize_kernel<<<(N_PTS + 255) / 256, 256>>>(b3, out);
}

// round 3
// speedup vs baseline: 2.6339x; 2.6339x over previous
#include <cuda_runtime.h>
#include <cuda_bf16.h>
#include <stdint.h>

#define N_PTS 2048
#define M_PTS 512
#define HID   128
#define TJ    64                  // j's per chunk
#define JT    (M_PTS / TJ)        // 8 chunks per i
#define NCHUNK (N_PTS * JT)       // 16384
#define NCTA  296                 // 2 per SM
#define PI_F  3.14159265358979323846f

// smem pitch: 136 bf16 per row = 272 B = 17 x 16B -> ldmatrix conflict-free
#define PITCH_B 272

// ---- shared memory layout (bytes) ----
#define SM_W2HI  0                      // [128][136] bf16  (W2^T hi) 34816 B
#define SM_W2LO  34816                  // 34816 B
#define SM_H1HI  69632                  // [64][136] bf16   17408 B
#define SM_H1LO  87040                  // 17408 B
#define SM_B2W3  104448                 // 128 x float2
#define SM_RED   105472                 // 8 floats
#define SMEM_TOTAL 105600

// ---- device scratch ----
__device__ __align__(16) float g_A[N_PTS * HID];
__device__ __align__(16) float g_B[M_PTS * HID];
__device__ __align__(16) float g_y[M_PTS];
__device__ float g_Y;
__device__ __align__(16) float g_part[NCHUNK];

// ---------------------------------------------------------------------------
__device__ __forceinline__ float tanh_fast(float x) {
    float e = __expf(2.0f * x);
    return 1.0f - __fdividef(2.0f, e + 1.0f);
}

__device__ __forceinline__ uint32_t smem_u32(const void* p) {
    uint32_t a;
    asm("{ .reg .u64 t; cvta.to.shared.u64 t, %1; cvt.u32.u64 %0, t; }"
        : "=r"(a) : "l"(p));
    return a;
}

__device__ __forceinline__ void ldsm4(uint32_t& r0, uint32_t& r1,
                                      uint32_t& r2, uint32_t& r3, uint32_t addr) {
    asm volatile("ldmatrix.sync.aligned.m8n8.x4.shared.b16 {%0,%1,%2,%3}, [%4];"
                 : "=r"(r0), "=r"(r1), "=r"(r2), "=r"(r3) : "r"(addr));
}

__device__ __forceinline__ void mma_bf16(float* d, const uint32_t* a,
                                         const uint32_t* b) {
    asm volatile(
        "mma.sync.aligned.m16n8k16.row.col.f32.bf16.bf16.f32 "
        "{%0,%1,%2,%3}, {%4,%5,%6,%7}, {%8,%9}, {%0,%1,%2,%3};"
        : "+f"(d[0]), "+f"(d[1]), "+f"(d[2]), "+f"(d[3])
        : "r"(a[0]), "r"(a[1]), "r"(a[2]), "r"(a[3]), "r"(b[0]), "r"(b[1]));
}

// split fp32 pair -> (bf16x2 hi, bf16x2 lo)
__device__ __forceinline__ void split2(float v0, float v1, uint32_t& hi, uint32_t& lo) {
    __nv_bfloat16 h0 = __float2bfloat16_rn(v0), h1 = __float2bfloat16_rn(v1);
    float r0 = v0 - __bfloat162float(h0);
    float r1 = v1 - __bfloat162float(h1);
    __nv_bfloat16 l0 = __float2bfloat16_rn(r0), l1 = __float2bfloat16_rn(r1);
    hi = ((uint32_t)__bfloat16_as_ushort(h1) << 16) | (uint32_t)__bfloat16_as_ushort(h0);
    lo = ((uint32_t)__bfloat16_as_ushort(l1) << 16) | (uint32_t)__bfloat16_as_ushort(l0);
}

// ---------------------------------------------------------------------------
__global__ void prep_ab_kernel(const float* __restrict__ inp,
                               const float* __restrict__ qx,
                               const float* __restrict__ W1,
                               const float* __restrict__ b1) {
    int idx = blockIdx.x * blockDim.x + threadIdx.x;
    const float4* W14 = (const float4*)W1;
    if (idx < N_PTS * 32) {
        int n = idx >> 5, v = idx & 31;
        float x0 = inp[2 * n], x1 = inp[2 * n + 1];
        float4 wa = W14[v], wb = W14[32 + v];
        float4 r;
        r.x = x0 * wa.x + x1 * wb.x;
        r.y = x0 * wa.y + x1 * wb.y;
        r.z = x0 * wa.z + x1 * wb.z;
        r.w = x0 * wa.w + x1 * wb.w;
        ((float4*)g_A)[idx] = r;
    } else {
        int t = idx - N_PTS * 32;
        if (t < M_PTS * 32) {
            int m = t >> 5, v = t & 31;
            float q0 = qx[2 * m], q1 = qx[2 * m + 1];
            float4 wc = W14[64 + v], wd = W14[96 + v];
            float4 bb = ((const float4*)b1)[v];
            float4 r;
            r.x = q0 * wc.x + q1 * wd.x + bb.x;
            r.y = q0 * wc.y + q1 * wd.y + bb.y;
            r.z = q0 * wc.z + q1 * wd.z + bb.z;
            r.w = q0 * wc.w + q1 * wd.w + bb.w;
            ((float4*)g_B)[t] = r;
        }
    }
}

__global__ void prep_y_kernel(const float* __restrict__ qx,
                              const float* __restrict__ ep) {
    __shared__ float red[512];
    int j = threadIdx.x;
    float e = ep[0];
    float y = sinf(PI_F * e * qx[2 * j]) * sinf(PI_F * e * qx[2 * j + 1]);
    g_y[j] = y;
    red[j] = y;
    __syncthreads();
    for (int s = 256; s > 0; s >>= 1) {
        if (j < s) red[j] += red[j + s];
        __syncthreads();
    }
    if (j == 0) g_Y = red[0];
}

// ---------------------------------------------------------------------------
// Main persistent kernel: tanh tiles -> 3-pass bf16 mma.sync -> fused epilogue
// 256 threads = 8 warps. Warp grid 2(m) x 4(n): warp tile = 32 j x 32 k.
// ---------------------------------------------------------------------------
__global__ void __launch_bounds__(256, 2) modnet_mma_kernel(
        const float* __restrict__ W2,
        const float* __restrict__ b2,
        const float* __restrict__ W3) {
    extern __shared__ char smem[];
    const uint32_t sb = smem_u32(smem);
    const int tid = threadIdx.x, lane = tid & 31, wid = tid >> 5;
    const int wm = wid & 1, wn = wid >> 1;

    // ---- prologue: W2^T hi/lo into smem (n rows, c contiguous) ----
    for (int e = tid; e < HID * 64; e += 256) {
        int n = e & 127, cp = e >> 7, c = cp * 2;
        float w0 = W2[c * HID + n], w1 = W2[(c + 1) * HID + n];
        uint32_t hi, lo;
        split2(w0, w1, hi, lo);
        uint32_t off = (uint32_t)(n * PITCH_B + cp * 4);
        *(uint32_t*)(smem + SM_W2HI + off) = hi;
        *(uint32_t*)(smem + SM_W2LO + off) = lo;
    }
    if (tid < HID) {
        float2 v; v.x = b2[tid]; v.y = W3[tid];
        *(float2*)(smem + SM_B2W3 + tid * 8) = v;
    }
    __syncthreads();

    // lane-invariant pieces of ldmatrix addressing
    const uint32_t a_row   = (uint32_t)(wm * 32 + (lane & 15));
    const uint32_t a_coff  = (uint32_t)((lane >> 4) * 16);          // bytes (8 bf16)
    const uint32_t aHbase  = sb + SM_H1HI + a_row * PITCH_B + a_coff;
    const uint32_t aLbase  = sb + SM_H1LO + a_row * PITCH_B + a_coff;
    const uint32_t b_n     = (uint32_t)(wn * 32 + ((lane >> 4) << 3) + (lane & 7));
    const uint32_t b_coff  = (uint32_t)(((lane >> 3) & 1) * 16);
    const uint32_t bHbase  = sb + SM_W2HI + b_n * PITCH_B + b_coff;
    const uint32_t bLbase  = sb + SM_W2LO + b_n * PITCH_B + b_coff;

    const float2* bw = (const float2*)(smem + SM_B2W3);
    float* red = (float*)(smem + SM_RED);

    for (int cid = blockIdx.x; cid < NCHUNK; cid += NCTA) {
        const int i  = cid >> 3;
        const int j0 = (cid & 7) * TJ;
        const float* Ai = g_A + i * HID;

        // ---- phase 1: h1 = tanh(A_i + B_j) -> bf16 hi/lo in smem ----
        #pragma unroll 4
        for (int e = tid; e < TJ * 64; e += 256) {
            int j = e >> 6, cp = e & 63, c = cp * 2;
            float2 a = *(const float2*)(Ai + c);
            float2 b = *(const float2*)(g_B + (j0 + j) * HID + c);
            float v0 = tanh_fast(a.x + b.x);
            float v1 = tanh_fast(a.y + b.y);
            uint32_t hi, lo;
            split2(v0, v1, hi, lo);
            uint32_t off = (uint32_t)(j * PITCH_B + cp * 4);
            *(uint32_t*)(smem + SM_H1HI + off) = hi;
            *(uint32_t*)(smem + SM_H1LO + off) = lo;
        }
        __syncthreads();

        // ---- phase 2: GEMM, warp tile 32x32, K=128, 3 bf16 passes ----
        float acc[2][4][4];
        #pragma unroll
        for (int mf = 0; mf < 2; mf++)
            #pragma unroll
            for (int nf = 0; nf < 4; nf++)
                #pragma unroll
                for (int q = 0; q < 4; q++) acc[mf][nf][q] = 0.0f;

        #pragma unroll 2
        for (int ks = 0; ks < 8; ks++) {
            const uint32_t kb = (uint32_t)(ks * 32);     // 16 bf16 = 32 bytes
            uint32_t ah[2][4], al[2][4], bh[4][2], bl[4][2];
            #pragma unroll
            for (int mf = 0; mf < 2; mf++) {
                uint32_t off = (uint32_t)(mf * 16 * PITCH_B) + kb;
                ldsm4(ah[mf][0], ah[mf][1], ah[mf][2], ah[mf][3], aHbase + off);
                ldsm4(al[mf][0], al[mf][1], al[mf][2], al[mf][3], aLbase + off);
            }
            #pragma unroll
            for (int np = 0; np < 2; np++) {             // n-frag pairs
                uint32_t off = (uint32_t)(np * 16 * PITCH_B) + kb;
                ldsm4(bh[np*2][0], bh[np*2][1], bh[np*2+1][0], bh[np*2+1][1], bHbase + off);
                ldsm4(bl[np*2][0], bl[np*2][1], bl[np*2+1][0], bl[np*2+1][1], bLbase + off);
            }
            #pragma unroll
            for (int mf = 0; mf < 2; mf++)
                #pragma unroll
                for (int nf = 0; nf < 4; nf++) {
                    mma_bf16(acc[mf][nf], ah[mf], bh[nf]);
                    mma_bf16(acc[mf][nf], al[mf], bh[nf]);
                    mma_bf16(acc[mf][nf], ah[mf], bl[nf]);
                }
        }

        // ---- phase 3: fused epilogue from registers ----
        const int r = lane >> 2, q2 = (lane & 3) * 2;
        float s = 0.0f;
        #pragma unroll
        for (int mf = 0; mf < 2; mf++) {
            const int jr = wm * 32 + mf * 16 + r;
            const float y0 = g_y[j0 + jr];
            const float y1 = g_y[j0 + jr + 8];
            #pragma unroll
            for (int nf = 0; nf < 4; nf++) {
                const int k = wn * 32 + nf * 8 + q2;
                float2 c0 = bw[k], c1 = bw[k + 1];
                s += y0 * (tanh_fast(acc[mf][nf][0] + c0.x) * c0.y
                         + tanh_fast(acc[mf][nf][1] + c1.x) * c1.y)
                   + y1 * (tanh_fast(acc[mf][nf][2] + c0.x) * c0.y
                         + tanh_fast(acc[mf][nf][3] + c1.x) * c1.y);
            }
        }
        #pragma unroll
        for (int o = 16; o > 0; o >>= 1) s += __shfl_xor_sync(0xffffffffu, s, o);
        if (lane == 0) red[wid] = s;
        __syncthreads();
        if (tid == 0) {
            float t = 0.0f;
            #pragma unroll
            for (int w = 0; w < 8; w++) t += red[w];     // fixed order
            g_part[cid] = t;
        }
        __syncthreads();    // red read done; h1 safe to overwrite next iter
    }
}

// ---------------------------------------------------------------------------
__global__ void finalize_kernel(const float* __restrict__ b3,
                                float* __restrict__ out) {
    int i = blockIdx.x * blockDim.x + threadIdx.x;
    if (i < N_PTS) {
        float s = b3[0] * g_Y;
        #pragma unroll
        for (int t = 0; t < JT; t++) s += g_part[i * JT + t];
        out[i] = s;
    }
}

// ---------------------------------------------------------------------------
extern "C" void kernel_launch(void* const* d_in, const int* in_sizes, int n_in,
                              void* d_out, int out_size) {
    const float* inp = (const float*)d_in[0];   // [2048, 2]
    const float* qx  = (const float*)d_in[1];   // [512, 2]
    const float* ep  = (const float*)d_in[2];   // [1]
    const float* W1  = (const float*)d_in[3];   // [4, 128]
    const float* b1  = (const float*)d_in[4];   // [128]
    const float* W2  = (const float*)d_in[5];   // [128, 128]
    const float* b2  = (const float*)d_in[6];   // [128]
    const float* W3  = (const float*)d_in[7];   // [128, 1]
    const float* b3  = (const float*)d_in[8];   // [1]
    float* out = (float*)d_out;                 // [2048, 1]
    (void)in_sizes; (void)n_in; (void)out_size;

    cudaFuncSetAttribute(modnet_mma_kernel,
                         cudaFuncAttributeMaxDynamicSharedMemorySize, SMEM_TOTAL);

    prep_ab_kernel<<<(N_PTS * 32 + M_PTS * 32 + 255) / 256, 256>>>(inp, qx, W1, b1);
    prep_y_kernel<<<1, 512>>>(qx, ep);
    modnet_mma_kernel<<<NCTA, 256, SMEM_TOTAL>>>(W2, b2, W3);
    finalize_kernel<<<(N_PTS + 255) / 256, 256>>>(b3, out);
}

// round 4
// speedup vs baseline: 3.6312x; 1.3787x over previous
#include <cuda_runtime.h>
#include <cuda_fp16.h>
#include <stdint.h>
#include <string.h>

#define N_PTS 2048
#define M_PTS 512
#define HID   128
#define TJ    64                  // j's per chunk
#define JT    (M_PTS / TJ)        // 8 chunks per i
#define NCHUNK (N_PTS * JT)       // 16384
#define NCTA  296                 // 2 per SM
#define PI_F  3.14159265358979323846f

// smem pitch: 136 fp16 per row = 272 B = 17 x 16B -> ldmatrix conflict-free
#define PITCH_B 272

// ---- shared memory layout (bytes) ----
#define SM_W2HI  0                      // [128][136] fp16 (W2^T hi) 34816 B
#define SM_H1HI  34816                  // [64][136] fp16  17408 B
#define SM_H1LO  52224                  // 17408 B
#define SM_B2W3  69632                  // 128 x float2
#define SM_RED   70656                  // 8 floats
#define SMEM_TOTAL 70784

// ---- device scratch ----
__device__ __align__(16) float g_A[N_PTS * HID];
__device__ __align__(16) float g_B[M_PTS * HID];
__device__ __align__(16) float g_y[M_PTS];
__device__ float g_Y;
__device__ __align__(16) float g_part[NCHUNK];

// ---------------------------------------------------------------------------
__device__ __forceinline__ float tanh_fast(float x) {
    float e = __expf(2.0f * x);
    return 1.0f - __fdividef(2.0f, e + 1.0f);
}

__device__ __forceinline__ uint32_t smem_u32(const void* p) {
    uint32_t a;
    asm("{ .reg .u64 t; cvta.to.shared.u64 t, %1; cvt.u32.u64 %0, t; }"
        : "=r"(a) : "l"(p));
    return a;
}

__device__ __forceinline__ void ldsm4(uint32_t& r0, uint32_t& r1,
                                      uint32_t& r2, uint32_t& r3, uint32_t addr) {
    asm volatile("ldmatrix.sync.aligned.m8n8.x4.shared.b16 {%0,%1,%2,%3}, [%4];"
                 : "=r"(r0), "=r"(r1), "=r"(r2), "=r"(r3) : "r"(addr));
}

__device__ __forceinline__ void mma_f16(float* d, const uint32_t* a,
                                        const uint32_t* b) {
    asm volatile(
        "mma.sync.aligned.m16n8k16.row.col.f32.f16.f16.f32 "
        "{%0,%1,%2,%3}, {%4,%5,%6,%7}, {%8,%9}, {%0,%1,%2,%3};"
        : "+f"(d[0]), "+f"(d[1]), "+f"(d[2]), "+f"(d[3])
        : "r"(a[0]), "r"(a[1]), "r"(a[2]), "r"(a[3]), "r"(b[0]), "r"(b[1]));
}

__device__ __forceinline__ uint32_t h2u(__half2 h) {
    uint32_t u; memcpy(&u, &h, 4); return u;
}

// fp32 pair -> packed fp16 hi + packed fp16 lo (residual)
__device__ __forceinline__ void split2h(float v0, float v1,
                                        uint32_t& hi, uint32_t& lo) {
    __half2 h = __floats2half2_rn(v0, v1);
    float2 hf = __half22float2(h);
    __half2 l = __floats2half2_rn(v0 - hf.x, v1 - hf.y);
    hi = h2u(h); lo = h2u(l);
}

// ---------------------------------------------------------------------------
__global__ void prep_ab_kernel(const float* __restrict__ inp,
                               const float* __restrict__ qx,
                               const float* __restrict__ W1,
                               const float* __restrict__ b1) {
    int idx = blockIdx.x * blockDim.x + threadIdx.x;
    const float4* W14 = (const float4*)W1;
    if (idx < N_PTS * 32) {
        int n = idx >> 5, v = idx & 31;
        float x0 = inp[2 * n], x1 = inp[2 * n + 1];
        float4 wa = W14[v], wb = W14[32 + v];
        float4 r;
        r.x = x0 * wa.x + x1 * wb.x;
        r.y = x0 * wa.y + x1 * wb.y;
        r.z = x0 * wa.z + x1 * wb.z;
        r.w = x0 * wa.w + x1 * wb.w;
        ((float4*)g_A)[idx] = r;
    } else {
        int t = idx - N_PTS * 32;
        if (t < M_PTS * 32) {
            int m = t >> 5, v = t & 31;
            float q0 = qx[2 * m], q1 = qx[2 * m + 1];
            float4 wc = W14[64 + v], wd = W14[96 + v];
            float4 bb = ((const float4*)b1)[v];
            float4 r;
            r.x = q0 * wc.x + q1 * wd.x + bb.x;
            r.y = q0 * wc.y + q1 * wd.y + bb.y;
            r.z = q0 * wc.z + q1 * wd.z + bb.z;
            r.w = q0 * wc.w + q1 * wd.w + bb.w;
            ((float4*)g_B)[t] = r;
        }
    }
}

__global__ void prep_y_kernel(const float* __restrict__ qx,
                              const float* __restrict__ ep) {
    __shared__ float red[512];
    int j = threadIdx.x;
    float e = ep[0];
    float y = sinf(PI_F * e * qx[2 * j]) * sinf(PI_F * e * qx[2 * j + 1]);
    g_y[j] = y;
    red[j] = y;
    __syncthreads();
    for (int s = 256; s > 0; s >>= 1) {
        if (j < s) red[j] += red[j + s];
        __syncthreads();
    }
    if (j == 0) g_Y = red[0];
}

// ---------------------------------------------------------------------------
// Main persistent kernel: tanh tiles -> 2-pass fp16 mma.sync -> fused epilogue
// 256 threads = 8 warps. Warp grid 2(m) x 4(n): warp tile = 32 j x 32 k.
// ---------------------------------------------------------------------------
__global__ void __launch_bounds__(256, 2) modnet_mma_kernel(
        const float* __restrict__ W2,
        const float* __restrict__ b2,
        const float* __restrict__ W3) {
    extern __shared__ char smem[];
    const uint32_t sb = smem_u32(smem);
    const int tid = threadIdx.x, lane = tid & 31, wid = tid >> 5;
    const int wm = wid & 1, wn = wid >> 1;

    // ---- prologue: W2^T (fp16 hi only) into smem ----
    for (int e = tid; e < HID * 64; e += 256) {
        int n = e & 127, cp = e >> 7, c = cp * 2;
        __half2 h = __floats2half2_rn(W2[c * HID + n], W2[(c + 1) * HID + n]);
        *(uint32_t*)(smem + SM_W2HI + (uint32_t)(n * PITCH_B + cp * 4)) = h2u(h);
    }
    if (tid < HID) {
        float2 v; v.x = b2[tid]; v.y = W3[tid];
        *(float2*)(smem + SM_B2W3 + tid * 8) = v;
    }
    __syncthreads();

    // lane-invariant ldmatrix addressing
    const uint32_t a_row   = (uint32_t)(wm * 32 + (lane & 15));
    const uint32_t a_coff  = (uint32_t)((lane >> 4) * 16);
    const uint32_t aHbase  = sb + SM_H1HI + a_row * PITCH_B + a_coff;
    const uint32_t aLbase  = sb + SM_H1LO + a_row * PITCH_B + a_coff;
    const uint32_t b_n     = (uint32_t)(wn * 32 + ((lane >> 4) << 3) + (lane & 7));
    const uint32_t b_coff  = (uint32_t)(((lane >> 3) & 1) * 16);
    const uint32_t bHbase  = sb + SM_W2HI + b_n * PITCH_B + b_coff;

    const float2* bw = (const float2*)(smem + SM_B2W3);
    float* red = (float*)(smem + SM_RED);

    for (int cid = blockIdx.x; cid < NCHUNK; cid += NCTA) {
        const int i  = cid >> 3;
        const int j0 = (cid & 7) * TJ;
        const float* Ai = g_A + i * HID;

        // ---- phase 1: h1 = tanh(A_i + B_j) -> fp16 hi/lo in smem ----
        #pragma unroll 2
        for (int e = tid; e < TJ * 32; e += 256) {     // 8 iters, 4 elems each
            int j = e >> 5, cp = e & 31, c = cp * 4;
            float4 a = *(const float4*)(Ai + c);
            float4 b = *(const float4*)(g_B + (j0 + j) * HID + c);
            float v0 = tanh_fast(a.x + b.x);
            float v1 = tanh_fast(a.y + b.y);
            float v2 = tanh_fast(a.z + b.z);
            float v3 = tanh_fast(a.w + b.w);
            uint32_t h0, l0, h1, l1;
            split2h(v0, v1, h0, l0);
            split2h(v2, v3, h1, l1);
            uint32_t off = (uint32_t)(j * PITCH_B + cp * 8);
            *(uint2*)(smem + SM_H1HI + off) = make_uint2(h0, h1);
            *(uint2*)(smem + SM_H1LO + off) = make_uint2(l0, l1);
        }
        __syncthreads();

        // ---- phase 2: GEMM, warp tile 32x32, K=128, 2 fp16 passes ----
        float acc[2][4][4];
        #pragma unroll
        for (int mf = 0; mf < 2; mf++)
            #pragma unroll
            for (int nf = 0; nf < 4; nf++)
                #pragma unroll
                for (int q = 0; q < 4; q++) acc[mf][nf][q] = 0.0f;

        #pragma unroll 2
        for (int ks = 0; ks < 8; ks++) {
            const uint32_t kb = (uint32_t)(ks * 32);     // 16 fp16 = 32 bytes
            uint32_t ah[2][4], al[2][4], bh[4][2];
            #pragma unroll
            for (int mf = 0; mf < 2; mf++) {
                uint32_t off = (uint32_t)(mf * 16 * PITCH_B) + kb;
                ldsm4(ah[mf][0], ah[mf][1], ah[mf][2], ah[mf][3], aHbase + off);
                ldsm4(al[mf][0], al[mf][1], al[mf][2], al[mf][3], aLbase + off);
            }
            #pragma unroll
            for (int np = 0; np < 2; np++) {
                uint32_t off = (uint32_t)(np * 16 * PITCH_B) + kb;
                ldsm4(bh[np*2][0], bh[np*2][1], bh[np*2+1][0], bh[np*2+1][1],
                      bHbase + off);
            }
            #pragma unroll
            for (int mf = 0; mf < 2; mf++)
                #pragma unroll
                for (int nf = 0; nf < 4; nf++) {
                    mma_f16(acc[mf][nf], ah[mf], bh[nf]);
                    mma_f16(acc[mf][nf], al[mf], bh[nf]);
                }
        }

        // ---- phase 3: fused epilogue from registers ----
        const int r = lane >> 2, q2 = (lane & 3) * 2;
        float s = 0.0f;
        #pragma unroll
        for (int mf = 0; mf < 2; mf++) {
            const int jr = wm * 32 + mf * 16 + r;
            const float y0 = g_y[j0 + jr];
            const float y1 = g_y[j0 + jr + 8];
            #pragma unroll
            for (int nf = 0; nf < 4; nf++) {
                const int k = wn * 32 + nf * 8 + q2;
                float2 c0 = bw[k], c1 = bw[k + 1];
                s += y0 * (tanh_fast(acc[mf][nf][0] + c0.x) * c0.y
                         + tanh_fast(acc[mf][nf][1] + c1.x) * c1.y)
                   + y1 * (tanh_fast(acc[mf][nf][2] + c0.x) * c0.y
                         + tanh_fast(acc[mf][nf][3] + c1.x) * c1.y);
            }
        }
        #pragma unroll
        for (int o = 16; o > 0; o >>= 1) s += __shfl_xor_sync(0xffffffffu, s, o);
        if (lane == 0) red[wid] = s;
        __syncthreads();
        if (tid == 0) {
            float t = 0.0f;
            #pragma unroll
            for (int w = 0; w < 8; w++) t += red[w];     // fixed order
            g_part[cid] = t;
        }
        __syncthreads();    // red consumed; h1 buffers reusable next iter
    }
}

// ---------------------------------------------------------------------------
__global__ void finalize_kernel(const float* __restrict__ b3,
                                float* __restrict__ out) {
    int i = blockIdx.x * blockDim.x + threadIdx.x;
    if (i < N_PTS) {
        float s = b3[0] * g_Y;
        #pragma unroll
        for (int t = 0; t < JT; t++) s += g_part[i * JT + t];
        out[i] = s;
    }
}

// ---------------------------------------------------------------------------
extern "C" void kernel_launch(void* const* d_in, const int* in_sizes, int n_in,
                              void* d_out, int out_size) {
    const float* inp = (const float*)d_in[0];   // [2048, 2]
    const float* qx  = (const float*)d_in[1];   // [512, 2]
    const float* ep  = (const float*)d_in[2];   // [1]
    const float* W1  = (const float*)d_in[3];   // [4, 128]
    const float* b1  = (const float*)d_in[4];   // [128]
    const float* W2  = (const float*)d_in[5];   // [128, 128]
    const float* b2  = (const float*)d_in[6];   // [128]
    const float* W3  = (const float*)d_in[7];   // [128, 1]
    const float* b3  = (const float*)d_in[8];   // [1]
    float* out = (float*)d_out;                 // [2048, 1]
    (void)in_sizes; (void)n_in; (void)out_size;

    cudaFuncSetAttribute(modnet_mma_kernel,
                         cudaFuncAttributeMaxDynamicSharedMemorySize, SMEM_TOTAL);

    prep_ab_kernel<<<(N_PTS * 32 + M_PTS * 32 + 255) / 256, 256>>>(inp, qx, W1, b1);
    prep_y_kernel<<<1, 512>>>(qx, ep);
    modnet_mma_kernel<<<NCTA, 256, SMEM_TOTAL>>>(W2, b2, W3);
    finalize_kernel<<<(N_PTS + 255) / 256, 256>>>(b3, out);
}